// round 7
// baseline (speedup 1.0000x reference)
#include <cuda_runtime.h>
#include <cuda_fp16.h>
#include <cstdint>

#define B_  8
#define T_  2048
#define D_  256
#define BQ  128
#define BK  32
#define NIT 64          // T_/BK
#define NTH 256

// ---- f16 hi/lo images of dec (Q) and enc (K), built by one pre-kernel -----
__device__ __align__(16) __half g_qhi[(size_t)B_*T_*D_];
__device__ __align__(16) __half g_qlo[(size_t)B_*T_*D_];
__device__ __align__(16) __half g_khi[(size_t)B_*T_*D_];
__device__ __align__(16) __half g_klo[(size_t)B_*T_*D_];

__device__ __forceinline__ uint32_t h2pack(__half a, __half b){
    return (uint32_t)__half_as_ushort(a) | ((uint32_t)__half_as_ushort(b) << 16);
}

// one pass over dec (also writes out[...,0:256]) and enc
__global__ void pk_all(const float* __restrict__ dec, const float* __restrict__ enc,
                       float* __restrict__ out){
    size_t g = (size_t)blockIdx.x * NTH + threadIdx.x;
    const size_t QU = (size_t)B_*T_*D_/4;
    const float4* src = (g < QU) ? (const float4*)dec : (const float4*)enc;
    size_t q = (g < QU) ? g : g - QU;
    float4 v = src[q];
    __half hx=__float2half_rn(v.x), hy=__float2half_rn(v.y);
    __half hz=__float2half_rn(v.z), hw=__float2half_rn(v.w);
    __half lx=__float2half_rn(v.x-__half2float(hx)), ly=__float2half_rn(v.y-__half2float(hy));
    __half lz=__float2half_rn(v.z-__half2float(hz)), lw=__float2half_rn(v.w-__half2float(hw));
    uint2 hi = make_uint2(h2pack(hx,hy), h2pack(hz,hw));
    uint2 lo = make_uint2(h2pack(lx,ly), h2pack(lz,lw));
    if (g < QU){
        ((uint2*)g_qhi)[q] = hi;  ((uint2*)g_qlo)[q] = lo;
        size_t row = q >> 6, c4 = q & 63;              // dec row copy -> out[...,0:256]
        ((float4*)out)[row*128 + c4] = v;
    } else {
        ((uint2*)g_khi)[q] = hi;  ((uint2*)g_klo)[q] = lo;
    }
}

// ---------------- base-ISA tensor / async primitives ----------------------
__device__ __forceinline__ void ldsm4(uint32_t r[4], uint32_t a){
    asm volatile("ldmatrix.sync.aligned.m8n8.x4.shared.b16 {%0,%1,%2,%3}, [%4];"
        : "=r"(r[0]),"=r"(r[1]),"=r"(r[2]),"=r"(r[3]) : "r"(a));
}
__device__ __forceinline__ void ldsm4t(uint32_t r[4], uint32_t a){
    asm volatile("ldmatrix.sync.aligned.m8n8.x4.trans.shared.b16 {%0,%1,%2,%3}, [%4];"
        : "=r"(r[0]),"=r"(r[1]),"=r"(r[2]),"=r"(r[3]) : "r"(a));
}
__device__ __forceinline__ void mma16816(float d[4], const uint32_t a[4], const uint32_t b[2]){
    asm volatile("mma.sync.aligned.m16n8k16.row.col.f32.f16.f16.f32 "
        "{%0,%1,%2,%3}, {%4,%5,%6,%7}, {%8,%9}, {%0,%1,%2,%3};"
        : "+f"(d[0]),"+f"(d[1]),"+f"(d[2]),"+f"(d[3])
        : "r"(a[0]),"r"(a[1]),"r"(a[2]),"r"(a[3]), "r"(b[0]),"r"(b[1]));
}
__device__ __forceinline__ void cpasync16(uint32_t dst, const void* src){
    uint64_t ga;
    asm volatile("cvta.to.global.u64 %0, %1;" : "=l"(ga) : "l"(src));
    asm volatile("cp.async.cg.shared.global [%0], [%1], 16;" :: "r"(dst), "l"(ga) : "memory");
}
#define CPCOMMIT() asm volatile("cp.async.commit_group;" ::: "memory")
#define CPWAIT1()  asm volatile("cp.async.wait_group 1;" ::: "memory")
#define CPWAIT0()  asm volatile("cp.async.wait_group 0;" ::: "memory")

// smem: padded rows of 264 halves (528 B) -> conflict-free ldmatrix
#define ROWB    528
#define SM_QHI  0
#define SM_QLO  (BQ*ROWB)             // 67584
#define SM_K0   (2*BQ*ROWB)           // 135168
#define STAGEB  (2*BK*ROWB)           // 33792 (hi 32 rows + lo 32 rows)
#define SM_TOT  (SM_K0 + 2*STAGEB)    // 202752

__global__ __launch_bounds__(NTH) void attn_main(float* __restrict__ out)
{
    extern __shared__ char smem[];
    const uint32_t smb = (uint32_t)__cvta_generic_to_shared(smem);
    const int tid = threadIdx.x, w = tid >> 5, lane = tid & 31;
    const int qt = blockIdx.x, b = blockIdx.y, t0 = qt * BQ;
    const int g = lane >> 3, lr = lane & 7;

    // per-thread stage-copy mapping: 8 uint4 per stage (2048 total: 1024 hi + 1024 lo)
    // issue stage `it` into buf (it&1)
    auto issue_stage = [&](int it){
        uint32_t base = smb + SM_K0 + (uint32_t)(it & 1) * STAGEB;
        int e0 = it * BK;
        #pragma unroll
        for (int k = 0; k < 8; k++){
            int i = tid + k * NTH;            // 0..2047
            int hl = i >> 10;                 // 0: hi, 1: lo
            int r  = (i >> 5) & 31, s = i & 31;
            uint32_t dst = base + (uint32_t)hl * (BK*ROWB) + (uint32_t)r*ROWB + (uint32_t)s*16;
            const __half* img = hl ? g_klo : g_khi;
            cpasync16(dst, img + ((size_t)(b*T_ + e0 + r))*D_ + s*8);
        }
        CPCOMMIT();
    };

    issue_stage(0);

    // ---- prologue: Q hi/lo tile -> smem
    {
        const uint4* qh = (const uint4*)(g_qhi + ((size_t)(b*T_ + t0))*D_);
        const uint4* ql = (const uint4*)(g_qlo + ((size_t)(b*T_ + t0))*D_);
        for (int i = tid; i < BQ*32; i += NTH){
            int r = i >> 5, s = i & 31;
            *(uint4*)(smem + SM_QHI + r*ROWB + s*16) = qh[r*32 + s];
            *(uint4*)(smem + SM_QLO + r*ROWB + s*16) = ql[r*32 + s];
        }
    }

    const uint32_t aQhi = smb + SM_QHI + (uint32_t)(16*w + (g&1)*8 + lr)*ROWB + (uint32_t)(g>>1)*16;
    const uint32_t aQlo = aQhi + (SM_QLO - SM_QHI);
    const uint32_t ob1  = (uint32_t)((g>>1)*8 + lr)*ROWB + (uint32_t)(g&1)*16;
    const uint32_t ob2  = (uint32_t)((g&1)*8 + lr)*ROWB + (uint32_t)(g>>1)*16;

    float mA = -1e30f, mB = -1e30f, lA = 0.f, lB = 0.f;
    float acc[32][4];
    #pragma unroll
    for (int j = 0; j < 32; j++){ acc[j][0]=0.f; acc[j][1]=0.f; acc[j][2]=0.f; acc[j][3]=0.f; }

    #pragma unroll 1
    for (int it = 0; it < NIT; it++){
        if (it + 1 < NIT){ issue_stage(it + 1); CPWAIT1(); } else { CPWAIT0(); }
        __syncthreads();   // stage `it` visible to all warps; prev buf free

        const uint32_t kb  = smb + SM_K0 + (uint32_t)(it & 1) * STAGEB;
        const uint32_t b1Hi = kb + ob1;
        const uint32_t b1Lo = b1Hi + (BK*ROWB);
        const uint32_t b2Hi = kb + ob2;

        // ---- GEMM1: S[16q x 32e] = Qhi*Khi + Qlo*Khi + Qhi*Klo ------------
        float S[4][4];
        #pragma unroll
        for (int j = 0; j < 4; j++){ S[j][0]=0.f; S[j][1]=0.f; S[j][2]=0.f; S[j][3]=0.f; }

        #pragma unroll
        for (int c = 0; c < 16; c++){
            uint32_t ah[4], al[4];
            ldsm4(ah, aQhi + 32u*c);
            ldsm4(al, aQlo + 32u*c);
            #pragma unroll
            for (int jj = 0; jj < 4; jj += 2){
                uint32_t bh[4], bl[4];
                ldsm4(bh, b1Hi + (uint32_t)jj*4224u + 32u*c);
                ldsm4(bl, b1Lo + (uint32_t)jj*4224u + 32u*c);
                mma16816(S[jj],   ah, bh);
                mma16816(S[jj],   al, bh);
                mma16816(S[jj],   ah, bl);
                mma16816(S[jj+1], ah, bh+2);
                mma16816(S[jj+1], al, bh+2);
                mma16816(S[jj+1], ah, bl+2);
            }
        }

        // ---- online softmax (rows rA=16w+(lane>>2), rB=rA+8) --------------
        float bmA = -1e30f, bmB = -1e30f;
        #pragma unroll
        for (int j = 0; j < 4; j++){
            bmA = fmaxf(bmA, fmaxf(S[j][0], S[j][1]));
            bmB = fmaxf(bmB, fmaxf(S[j][2], S[j][3]));
        }
        bmA = fmaxf(bmA, __shfl_xor_sync(0xffffffffu, bmA, 1));
        bmA = fmaxf(bmA, __shfl_xor_sync(0xffffffffu, bmA, 2));
        bmB = fmaxf(bmB, __shfl_xor_sync(0xffffffffu, bmB, 1));
        bmB = fmaxf(bmB, __shfl_xor_sync(0xffffffffu, bmB, 2));

        float mnA = fmaxf(mA, bmA), mnB = fmaxf(mB, bmB);
        float alphaA = __expf(mA - mnA), alphaB = __expf(mB - mnB);
        mA = mnA; mB = mnB;

        uint32_t ph[4][2];
        float sA = 0.f, sB = 0.f;
        #pragma unroll
        for (int j = 0; j < 4; j++){
            float p0 = __expf(S[j][0] - mnA), p1 = __expf(S[j][1] - mnA);
            float p2 = __expf(S[j][2] - mnB), p3 = __expf(S[j][3] - mnB);
            __half2 hA = __floats2half2_rn(p0, p1);
            __half2 hB = __floats2half2_rn(p2, p3);
            float2 fA = __half22float2(hA), fB = __half22float2(hB);
            sA += fA.x + fA.y;  sB += fB.x + fB.y;   // sum exactly what GEMM2 sees
            ph[j][0] = *(uint32_t*)&hA;
            ph[j][1] = *(uint32_t*)&hB;
        }
        sA += __shfl_xor_sync(0xffffffffu, sA, 1);
        sA += __shfl_xor_sync(0xffffffffu, sA, 2);
        sB += __shfl_xor_sync(0xffffffffu, sB, 1);
        sB += __shfl_xor_sync(0xffffffffu, sB, 2);
        lA = lA * alphaA + sA;
        lB = lB * alphaB + sB;

        if (!__all_sync(0xffffffffu, (alphaA == 1.f) & (alphaB == 1.f))){
            #pragma unroll
            for (int j = 0; j < 32; j++){
                acc[j][0] *= alphaA; acc[j][1] *= alphaA;
                acc[j][2] *= alphaB; acc[j][3] *= alphaB;
            }
        }

        // ---- GEMM2: acc[16q x 256d] += P[16q x 32e] * K[32e x 256d] -------
        #pragma unroll
        for (int kc = 0; kc < 2; kc++){
            uint32_t a[4] = { ph[2*kc][0], ph[2*kc][1], ph[2*kc+1][0], ph[2*kc+1][1] };
            #pragma unroll
            for (int jj = 0; jj < 32; jj += 2){
                uint32_t bb[4];
                ldsm4t(bb, b2Hi + (uint32_t)kc*8448u + (uint32_t)jj*16u);
                mma16816(acc[jj],   a, bb);
                mma16816(acc[jj+1], a, bb+2);
            }
        }
        __syncthreads();   // all warps done reading stage `it` before it's overwritten
    }

    // ---- epilogue: out[.., 256:512] = acc / l (dec half written by pk_all)
    {
        int rA = 16*w + (lane >> 2);
        float ivA = 1.f / lA, ivB = 1.f / lB;
        float* oA = out + ((size_t)(b*T_ + t0 + rA))    *(size_t)(2*D_) + D_ + (lane&3)*2;
        float* oB = out + ((size_t)(b*T_ + t0 + rA + 8))*(size_t)(2*D_) + D_ + (lane&3)*2;
        #pragma unroll
        for (int j = 0; j < 32; j++){
            *(float2*)(oA + 8*j) = make_float2(acc[j][0]*ivA, acc[j][1]*ivA);
            *(float2*)(oB + 8*j) = make_float2(acc[j][2]*ivB, acc[j][3]*ivB);
        }
    }
}

extern "C" void kernel_launch(void* const* d_in, const int* in_sizes, int n_in,
                              void* d_out, int out_size)
{
    const float* enc = (const float*)d_in[0];  // encoder_outputs [8,2048,256]
    const float* dec = (const float*)d_in[1];  // decoder_outputs [8,2048,256]
    float* out = (float*)d_out;                // [8,2048,512]
    (void)in_sizes; (void)n_in; (void)out_size;

    const int quads2 = 2 * B_*T_*D_/4;         // dec + enc quads
    pk_all<<<quads2/NTH, NTH>>>(dec, enc, out);

    cudaFuncSetAttribute(attn_main, cudaFuncAttributeMaxDynamicSharedMemorySize, SM_TOT);
    dim3 grid(T_/BQ, B_);                      // (16, 8) = 128 CTAs, single wave
    attn_main<<<grid, NTH, SM_TOT>>>(out);
}

// round 8
// speedup vs baseline: 1.1166x; 1.1166x over previous
#include <cuda_runtime.h>
#include <cuda_fp16.h>
#include <cstdint>

#define B_  8
#define T_  2048
#define D_  256
#define BQ  128
#define BK  64
#define NIT 32          // T_/BK
#define NTH 256

// ---- f16 hi/lo images of dec (Q) and enc (K), built by one pre-kernel -----
__device__ __align__(16) __half g_qhi[(size_t)B_*T_*D_];
__device__ __align__(16) __half g_qlo[(size_t)B_*T_*D_];
__device__ __align__(16) __half g_khi[(size_t)B_*T_*D_];
__device__ __align__(16) __half g_klo[(size_t)B_*T_*D_];

__device__ __forceinline__ uint32_t h2pack(__half a, __half b){
    return (uint32_t)__half_as_ushort(a) | ((uint32_t)__half_as_ushort(b) << 16);
}

// one pass over dec (also writes out[...,0:256]) and enc
__global__ void pk_all(const float* __restrict__ dec, const float* __restrict__ enc,
                       float* __restrict__ out){
    size_t g = (size_t)blockIdx.x * NTH + threadIdx.x;
    const size_t QU = (size_t)B_*T_*D_/4;
    const float4* src = (g < QU) ? (const float4*)dec : (const float4*)enc;
    size_t q = (g < QU) ? g : g - QU;
    float4 v = src[q];
    __half hx=__float2half_rn(v.x), hy=__float2half_rn(v.y);
    __half hz=__float2half_rn(v.z), hw=__float2half_rn(v.w);
    __half lx=__float2half_rn(v.x-__half2float(hx)), ly=__float2half_rn(v.y-__half2float(hy));
    __half lz=__float2half_rn(v.z-__half2float(hz)), lw=__float2half_rn(v.w-__half2float(hw));
    uint2 hi = make_uint2(h2pack(hx,hy), h2pack(hz,hw));
    uint2 lo = make_uint2(h2pack(lx,ly), h2pack(lz,lw));
    if (g < QU){
        ((uint2*)g_qhi)[q] = hi;  ((uint2*)g_qlo)[q] = lo;
        size_t row = q >> 6, c4 = q & 63;              // dec row copy -> out[...,0:256]
        ((float4*)out)[row*128 + c4] = v;
    } else {
        ((uint2*)g_khi)[q] = hi;  ((uint2*)g_klo)[q] = lo;
    }
}

// ---------------- base-ISA tensor / async primitives ----------------------
__device__ __forceinline__ void ldsm4(uint32_t r[4], uint32_t a){
    asm volatile("ldmatrix.sync.aligned.m8n8.x4.shared.b16 {%0,%1,%2,%3}, [%4];"
        : "=r"(r[0]),"=r"(r[1]),"=r"(r[2]),"=r"(r[3]) : "r"(a));
}
__device__ __forceinline__ void ldsm4t(uint32_t r[4], uint32_t a){
    asm volatile("ldmatrix.sync.aligned.m8n8.x4.trans.shared.b16 {%0,%1,%2,%3}, [%4];"
        : "=r"(r[0]),"=r"(r[1]),"=r"(r[2]),"=r"(r[3]) : "r"(a));
}
__device__ __forceinline__ void mma16816(float d[4], const uint32_t a[4], const uint32_t b[2]){
    asm volatile("mma.sync.aligned.m16n8k16.row.col.f32.f16.f16.f32 "
        "{%0,%1,%2,%3}, {%4,%5,%6,%7}, {%8,%9}, {%0,%1,%2,%3};"
        : "+f"(d[0]),"+f"(d[1]),"+f"(d[2]),"+f"(d[3])
        : "r"(a[0]),"r"(a[1]),"r"(a[2]),"r"(a[3]), "r"(b[0]),"r"(b[1]));
}
__device__ __forceinline__ void cpasync16(uint32_t dst, const void* src){
    uint64_t ga;
    asm volatile("cvta.to.global.u64 %0, %1;" : "=l"(ga) : "l"(src));
    asm volatile("cp.async.cg.shared.global [%0], [%1], 16;" :: "r"(dst), "l"(ga) : "memory");
}
#define CPCOMMIT() asm volatile("cp.async.commit_group;" ::: "memory")
#define CPWAIT0()  asm volatile("cp.async.wait_group 0;" ::: "memory")

// ---- swizzled smem layout: rows of exactly 512 B; 16B-col s -> s^(r&7) ----
// element (row r, 16B-chunk s): off = r*512 + ((s ^ (r&7))<<4)
#define SM_QHI  0                    // 128 rows = 65536
#define SM_QLO  65536                // 128 rows = 65536
#define SM_KHI0 131072               // 64 rows  = 32768 (stage 0)
#define SM_KHI1 163840               // 64 rows  = 32768 (stage 1)
#define SM_KLO  196608               // 64 rows  = 32768 (single buffer)
#define SM_TOT  229376               // <= 232448

__global__ __launch_bounds__(NTH) void attn_main(float* __restrict__ out)
{
    extern __shared__ char smem[];
    const uint32_t smb = (uint32_t)__cvta_generic_to_shared(smem);
    const int tid = threadIdx.x, w = tid >> 5, lane = tid & 31;
    const int qt = blockIdx.x, b = blockIdx.y, t0 = qt * BQ;
    const int g = lane >> 3, lr = lane & 7;

    // stage copy: 2048 uint4 per image (64 rows x 32 chunks), 8 per thread
    auto issue_khi = [&](int it){
        uint32_t base = smb + ((it & 1) ? SM_KHI1 : SM_KHI0);
        int e0 = it * BK;
        #pragma unroll
        for (int k = 0; k < 8; k++){
            int i = tid + k * NTH;               // 0..2047
            int r = i >> 5, s = i & 31;
            uint32_t dst = base + (uint32_t)r*512u + (uint32_t)((s ^ (r & 7)) << 4);
            cpasync16(dst, g_khi + ((size_t)(b*T_ + e0 + r))*D_ + s*8);
        }
        CPCOMMIT();
    };
    auto issue_klo = [&](int it){
        uint32_t base = smb + SM_KLO;
        int e0 = it * BK;
        #pragma unroll
        for (int k = 0; k < 8; k++){
            int i = tid + k * NTH;
            int r = i >> 5, s = i & 31;
            uint32_t dst = base + (uint32_t)r*512u + (uint32_t)((s ^ (r & 7)) << 4);
            cpasync16(dst, g_klo + ((size_t)(b*T_ + e0 + r))*D_ + s*8);
        }
        CPCOMMIT();
    };

    issue_khi(0);
    issue_klo(0);

    // ---- prologue: Q hi/lo tile -> swizzled smem (synchronous, once) ------
    {
        const uint4* qh = (const uint4*)(g_qhi + ((size_t)(b*T_ + t0))*D_);
        const uint4* ql = (const uint4*)(g_qlo + ((size_t)(b*T_ + t0))*D_);
        for (int i = tid; i < BQ*32; i += NTH){
            int r = i >> 5, s = i & 31;
            uint32_t off = (uint32_t)r*512u + (uint32_t)((s ^ (r & 7)) << 4);
            *(uint4*)(smem + SM_QHI + off) = qh[(size_t)r*32 + s];
            *(uint4*)(smem + SM_QLO + off) = ql[(size_t)r*32 + s];
        }
    }

    // per-thread fragment row bases (all rows == lr mod 8 -> xor key is lr)
    const uint32_t qhiR = smb + SM_QHI + (uint32_t)(16*w + (g&1)*8 + lr)*512u;
    const uint32_t qloR = qhiR + (SM_QLO - SM_QHI);
    const uint32_t kr1  = (uint32_t)((g>>1)*8 + lr)*512u;   // GEMM1 B rows (+16*jj)
    const uint32_t kr2  = (uint32_t)((g&1)*8 + lr)*512u;    // GEMM2 B rows (+16*kc)

    float mA = -1e30f, mB = -1e30f, lA = 0.f, lB = 0.f;
    float acc[32][4];
    #pragma unroll
    for (int j = 0; j < 32; j++){ acc[j][0]=0.f; acc[j][1]=0.f; acc[j][2]=0.f; acc[j][3]=0.f; }

    #pragma unroll 1
    for (int it = 0; it < NIT; it++){
        CPWAIT0();            // khi(it) + klo(it) arrived
        __syncthreads();      // visible to all warps; khi buf (it+1)&1 free (readers of it-1 done)

        if (it + 1 < NIT) issue_khi(it + 1);

        const uint32_t kb  = smb + ((it & 1) ? SM_KHI1 : SM_KHI0);
        const uint32_t klo = smb + SM_KLO;

        // ---- GEMM1: S[16q x 64e] = Qhi*Khi + Qlo*Khi + Qhi*Klo ------------
        float S[8][4];
        #pragma unroll
        for (int j = 0; j < 8; j++){ S[j][0]=0.f; S[j][1]=0.f; S[j][2]=0.f; S[j][3]=0.f; }

        #pragma unroll
        for (int c = 0; c < 16; c++){
            uint32_t qoff = (uint32_t)((((g>>1) + 2*c) ^ lr) << 4);
            uint32_t ah[4], al[4];
            ldsm4(ah, qhiR + qoff);
            ldsm4(al, qloR + qoff);
            uint32_t koff = (uint32_t)((((g&1) + 2*c) ^ lr) << 4);
            #pragma unroll
            for (int jj = 0; jj < 8; jj += 2){
                uint32_t rof = kr1 + (uint32_t)jj*4096u;   // +16 rows per jj step
                uint32_t bh[4], bl[4];
                ldsm4(bh, kb  + rof + koff);
                ldsm4(bl, klo + rof + koff);
                mma16816(S[jj],   ah, bh);
                mma16816(S[jj],   al, bh);
                mma16816(S[jj],   ah, bl);
                mma16816(S[jj+1], ah, bh+2);
                mma16816(S[jj+1], al, bh+2);
                mma16816(S[jj+1], ah, bl+2);
            }
        }
        __syncthreads();                      // all warps done reading Klo(it)
        if (it + 1 < NIT) issue_klo(it + 1);  // overlaps softmax + GEMM2

        // ---- online softmax (rows rA=16w+(lane>>2), rB=rA+8) --------------
        float bmA = -1e30f, bmB = -1e30f;
        #pragma unroll
        for (int j = 0; j < 8; j++){
            bmA = fmaxf(bmA, fmaxf(S[j][0], S[j][1]));
            bmB = fmaxf(bmB, fmaxf(S[j][2], S[j][3]));
        }
        bmA = fmaxf(bmA, __shfl_xor_sync(0xffffffffu, bmA, 1));
        bmA = fmaxf(bmA, __shfl_xor_sync(0xffffffffu, bmA, 2));
        bmB = fmaxf(bmB, __shfl_xor_sync(0xffffffffu, bmB, 1));
        bmB = fmaxf(bmB, __shfl_xor_sync(0xffffffffu, bmB, 2));

        float mnA = fmaxf(mA, bmA), mnB = fmaxf(mB, bmB);
        float alphaA = __expf(mA - mnA), alphaB = __expf(mB - mnB);
        mA = mnA; mB = mnB;

        uint32_t ph[8][2];
        float sA = 0.f, sB = 0.f;
        #pragma unroll
        for (int j = 0; j < 8; j++){
            float p0 = __expf(S[j][0] - mnA), p1 = __expf(S[j][1] - mnA);
            float p2 = __expf(S[j][2] - mnB), p3 = __expf(S[j][3] - mnB);
            __half2 hA = __floats2half2_rn(p0, p1);
            __half2 hB = __floats2half2_rn(p2, p3);
            float2 fA = __half22float2(hA), fB = __half22float2(hB);
            sA += fA.x + fA.y;  sB += fB.x + fB.y;   // sum exactly what GEMM2 sees
            ph[j][0] = *(uint32_t*)&hA;
            ph[j][1] = *(uint32_t*)&hB;
        }
        sA += __shfl_xor_sync(0xffffffffu, sA, 1);
        sA += __shfl_xor_sync(0xffffffffu, sA, 2);
        sB += __shfl_xor_sync(0xffffffffu, sB, 1);
        sB += __shfl_xor_sync(0xffffffffu, sB, 2);
        lA = lA * alphaA + sA;
        lB = lB * alphaB + sB;

        if (!__all_sync(0xffffffffu, (alphaA == 1.f) & (alphaB == 1.f))){
            #pragma unroll
            for (int j = 0; j < 32; j++){
                acc[j][0] *= alphaA; acc[j][1] *= alphaA;
                acc[j][2] *= alphaB; acc[j][3] *= alphaB;
            }
        }

        // ---- GEMM2: acc[16q x 256d] += P[16q x 64e] * Khi[64e x 256d] -----
        #pragma unroll
        for (int kc = 0; kc < 4; kc++){
            uint32_t a[4] = { ph[2*kc][0], ph[2*kc][1], ph[2*kc+1][0], ph[2*kc+1][1] };
            uint32_t rof = kr2 + (uint32_t)kc*8192u;       // +16 rows per kc
            #pragma unroll
            for (int jj = 0; jj < 32; jj += 2){
                uint32_t bb[4];
                ldsm4t(bb, kb + rof + (uint32_t)((((g>>1) + jj) ^ lr) << 4));
                mma16816(acc[jj],   a, bb);
                mma16816(acc[jj+1], a, bb+2);
            }
        }
        // no bottom sync: top-of-next-iter sync protects khi buf reuse
    }

    // ---- epilogue: out[.., 256:512] = acc / l (dec half written by pk_all)
    {
        int rA = 16*w + (lane >> 2);
        float ivA = 1.f / lA, ivB = 1.f / lB;
        float* oA = out + ((size_t)(b*T_ + t0 + rA))    *(size_t)(2*D_) + D_ + (lane&3)*2;
        float* oB = out + ((size_t)(b*T_ + t0 + rA + 8))*(size_t)(2*D_) + D_ + (lane&3)*2;
        #pragma unroll
        for (int j = 0; j < 32; j++){
            *(float2*)(oA + 8*j) = make_float2(acc[j][0]*ivA, acc[j][1]*ivA);
            *(float2*)(oB + 8*j) = make_float2(acc[j][2]*ivB, acc[j][3]*ivB);
        }
    }
}

extern "C" void kernel_launch(void* const* d_in, const int* in_sizes, int n_in,
                              void* d_out, int out_size)
{
    const float* enc = (const float*)d_in[0];  // encoder_outputs [8,2048,256]
    const float* dec = (const float*)d_in[1];  // decoder_outputs [8,2048,256]
    float* out = (float*)d_out;                // [8,2048,512]
    (void)in_sizes; (void)n_in; (void)out_size;

    const int quads2 = 2 * B_*T_*D_/4;         // dec + enc quads
    pk_all<<<quads2/NTH, NTH>>>(dec, enc, out);

    cudaFuncSetAttribute(attn_main, cudaFuncAttributeMaxDynamicSharedMemorySize, SM_TOT);
    dim3 grid(T_/BQ, B_);                      // (16, 8) = 128 CTAs, single wave
    attn_main<<<grid, NTH, SM_TOT>>>(out);
}

// round 9
// speedup vs baseline: 1.1785x; 1.0554x over previous
#include <cuda_runtime.h>
#include <cuda_fp16.h>
#include <cstdint>

#define B_  8
#define T_  2048
#define D_  256
#define BQ  128
#define BK  64
#define NIT 32          // T_/BK
#define NTH 256

// ---- f16 hi/lo images of dec (Q) and enc (K), built by one pre-kernel -----
__device__ __align__(16) __half g_qhi[(size_t)B_*T_*D_];
__device__ __align__(16) __half g_qlo[(size_t)B_*T_*D_];
__device__ __align__(16) __half g_khi[(size_t)B_*T_*D_];
__device__ __align__(16) __half g_klo[(size_t)B_*T_*D_];

__device__ __forceinline__ uint32_t h2pack(__half a, __half b){
    return (uint32_t)__half_as_ushort(a) | ((uint32_t)__half_as_ushort(b) << 16);
}

// one pass over dec (also writes out[...,0:256]) and enc
__global__ void pk_all(const float* __restrict__ dec, const float* __restrict__ enc,
                       float* __restrict__ out){
    size_t g = (size_t)blockIdx.x * NTH + threadIdx.x;
    const size_t QU = (size_t)B_*T_*D_/4;
    const float4* src = (g < QU) ? (const float4*)dec : (const float4*)enc;
    size_t q = (g < QU) ? g : g - QU;
    float4 v = src[q];
    __half hx=__float2half_rn(v.x), hy=__float2half_rn(v.y);
    __half hz=__float2half_rn(v.z), hw=__float2half_rn(v.w);
    __half lx=__float2half_rn(v.x-__half2float(hx)), ly=__float2half_rn(v.y-__half2float(hy));
    __half lz=__float2half_rn(v.z-__half2float(hz)), lw=__float2half_rn(v.w-__half2float(hw));
    uint2 hi = make_uint2(h2pack(hx,hy), h2pack(hz,hw));
    uint2 lo = make_uint2(h2pack(lx,ly), h2pack(lz,lw));
    if (g < QU){
        ((uint2*)g_qhi)[q] = hi;  ((uint2*)g_qlo)[q] = lo;
        size_t row = q >> 6, c4 = q & 63;              // dec row copy -> out[...,0:256]
        ((float4*)out)[row*128 + c4] = v;
    } else {
        ((uint2*)g_khi)[q] = hi;  ((uint2*)g_klo)[q] = lo;
    }
}

// ---------------- base-ISA tensor / async primitives ----------------------
__device__ __forceinline__ void ldsm4(uint32_t r[4], uint32_t a){
    asm volatile("ldmatrix.sync.aligned.m8n8.x4.shared.b16 {%0,%1,%2,%3}, [%4];"
        : "=r"(r[0]),"=r"(r[1]),"=r"(r[2]),"=r"(r[3]) : "r"(a));
}
__device__ __forceinline__ void ldsm4t(uint32_t r[4], uint32_t a){
    asm volatile("ldmatrix.sync.aligned.m8n8.x4.trans.shared.b16 {%0,%1,%2,%3}, [%4];"
        : "=r"(r[0]),"=r"(r[1]),"=r"(r[2]),"=r"(r[3]) : "r"(a));
}
__device__ __forceinline__ void mma16816(float d[4], const uint32_t a[4], const uint32_t b[2]){
    asm volatile("mma.sync.aligned.m16n8k16.row.col.f32.f16.f16.f32 "
        "{%0,%1,%2,%3}, {%4,%5,%6,%7}, {%8,%9}, {%0,%1,%2,%3};"
        : "+f"(d[0]),"+f"(d[1]),"+f"(d[2]),"+f"(d[3])
        : "r"(a[0]),"r"(a[1]),"r"(a[2]),"r"(a[3]), "r"(b[0]),"r"(b[1]));
}
__device__ __forceinline__ void cpasync16(uint32_t dst, const void* src){
    uint64_t ga;
    asm volatile("cvta.to.global.u64 %0, %1;" : "=l"(ga) : "l"(src));
    asm volatile("cp.async.cg.shared.global [%0], [%1], 16;" :: "r"(dst), "l"(ga) : "memory");
}
#define CPCOMMIT() asm volatile("cp.async.commit_group;" ::: "memory")
#define CPWAIT0()  asm volatile("cp.async.wait_group 0;" ::: "memory")

// ---- swizzled smem layout: rows of exactly 512 B; 16B-col s -> s^(r&7) ----
#define SM_QHI  0                    // 128 rows = 65536
#define SM_QLO  65536                // 128 rows = 65536
#define SM_KHI0 131072               // 64 rows  = 32768 (stage 0)
#define SM_KHI1 163840               // 64 rows  = 32768 (stage 1)
#define SM_KLO  196608               // 64 rows  = 32768 (single buffer)
#define SM_TOT  229376               // <= 232448

__global__ __launch_bounds__(NTH) void attn_main(float* __restrict__ out)
{
    extern __shared__ char smem[];
    const uint32_t smb = (uint32_t)__cvta_generic_to_shared(smem);
    const int tid = threadIdx.x, w = tid >> 5, lane = tid & 31;
    const int qt = blockIdx.x, b = blockIdx.y, t0 = qt * BQ;
    const int g = lane >> 3, lr = lane & 7;

    auto issue_khi = [&](int it){
        uint32_t base = smb + ((it & 1) ? SM_KHI1 : SM_KHI0);
        int e0 = it * BK;
        #pragma unroll
        for (int k = 0; k < 8; k++){
            int i = tid + k * NTH;
            int r = i >> 5, s = i & 31;
            uint32_t dst = base + (uint32_t)r*512u + (uint32_t)((s ^ (r & 7)) << 4);
            cpasync16(dst, g_khi + ((size_t)(b*T_ + e0 + r))*D_ + s*8);
        }
        CPCOMMIT();
    };
    auto issue_klo = [&](int it){
        uint32_t base = smb + SM_KLO;
        int e0 = it * BK;
        #pragma unroll
        for (int k = 0; k < 8; k++){
            int i = tid + k * NTH;
            int r = i >> 5, s = i & 31;
            uint32_t dst = base + (uint32_t)r*512u + (uint32_t)((s ^ (r & 7)) << 4);
            cpasync16(dst, g_klo + ((size_t)(b*T_ + e0 + r))*D_ + s*8);
        }
        CPCOMMIT();
    };

    issue_khi(0);
    issue_klo(0);

    // ---- prologue: Q hi/lo tile -> swizzled smem ---------------------------
    {
        const uint4* qh = (const uint4*)(g_qhi + ((size_t)(b*T_ + t0))*D_);
        const uint4* ql = (const uint4*)(g_qlo + ((size_t)(b*T_ + t0))*D_);
        for (int i = tid; i < BQ*32; i += NTH){
            int r = i >> 5, s = i & 31;
            uint32_t off = (uint32_t)r*512u + (uint32_t)((s ^ (r & 7)) << 4);
            *(uint4*)(smem + SM_QHI + off) = qh[(size_t)r*32 + s];
            *(uint4*)(smem + SM_QLO + off) = ql[(size_t)r*32 + s];
        }
    }

    const uint32_t qhiR = smb + SM_QHI + (uint32_t)(16*w + (g&1)*8 + lr)*512u;
    const uint32_t qloR = qhiR + (SM_QLO - SM_QHI);
    const uint32_t kr1  = (uint32_t)((g>>1)*8 + lr)*512u;   // GEMM1 B rows (+16*jj)
    const uint32_t kr2  = (uint32_t)((g&1)*8 + lr)*512u;    // GEMM2 B rows (+16*kc)

    float mA = -1e30f, mB = -1e30f, lA = 0.f, lB = 0.f;
    float acc[32][4];
    #pragma unroll
    for (int j = 0; j < 32; j++){ acc[j][0]=0.f; acc[j][1]=0.f; acc[j][2]=0.f; acc[j][3]=0.f; }

    #pragma unroll 1
    for (int it = 0; it < NIT; it++){
        CPWAIT0();
        __syncthreads();

        if (it + 1 < NIT) issue_khi(it + 1);

        const uint32_t kb  = smb + ((it & 1) ? SM_KHI1 : SM_KHI0);
        const uint32_t klo = smb + SM_KLO;

        // ---- GEMM1: S[16q x 64e] = Qhi*Khi + Qlo*Khi + Qhi*Klo ------------
        // Emission order per c-step: load ALL B frags, then 8x hh, 8x lh, 8x hl
        // -> dependent writes to each S[jj] are 8 MMAs (~32 cyc) apart.
        float S[8][4];
        #pragma unroll
        for (int j = 0; j < 8; j++){ S[j][0]=0.f; S[j][1]=0.f; S[j][2]=0.f; S[j][3]=0.f; }

        #pragma unroll
        for (int c = 0; c < 16; c++){
            uint32_t qoff = (uint32_t)((((g>>1) + 2*c) ^ lr) << 4);
            uint32_t ah[4], al[4];
            ldsm4(ah, qhiR + qoff);
            ldsm4(al, qloR + qoff);
            uint32_t koff = (uint32_t)((((g&1) + 2*c) ^ lr) << 4);
            uint32_t bh[4][4], bl[4][4];
            #pragma unroll
            for (int p = 0; p < 4; p++){
                uint32_t rof = kr1 + (uint32_t)p*8192u;    // +16 rows per jj-pair
                ldsm4(bh[p], kb  + rof + koff);
                ldsm4(bl[p], klo + rof + koff);
            }
            #pragma unroll
            for (int p = 0; p < 4; p++){                   // hh wave
                mma16816(S[2*p],   ah, bh[p]);
                mma16816(S[2*p+1], ah, bh[p]+2);
            }
            #pragma unroll
            for (int p = 0; p < 4; p++){                   // lh wave
                mma16816(S[2*p],   al, bh[p]);
                mma16816(S[2*p+1], al, bh[p]+2);
            }
            #pragma unroll
            for (int p = 0; p < 4; p++){                   // hl wave
                mma16816(S[2*p],   ah, bl[p]);
                mma16816(S[2*p+1], ah, bl[p]+2);
            }
        }
        __syncthreads();                      // all warps done reading Klo(it)
        if (it + 1 < NIT) issue_klo(it + 1);  // overlaps softmax + GEMM2

        // ---- online softmax (rows rA=16w+(lane>>2), rB=rA+8) --------------
        float bmA = -1e30f, bmB = -1e30f;
        #pragma unroll
        for (int j = 0; j < 8; j++){
            bmA = fmaxf(bmA, fmaxf(S[j][0], S[j][1]));
            bmB = fmaxf(bmB, fmaxf(S[j][2], S[j][3]));
        }
        bmA = fmaxf(bmA, __shfl_xor_sync(0xffffffffu, bmA, 1));
        bmA = fmaxf(bmA, __shfl_xor_sync(0xffffffffu, bmA, 2));
        bmB = fmaxf(bmB, __shfl_xor_sync(0xffffffffu, bmB, 1));
        bmB = fmaxf(bmB, __shfl_xor_sync(0xffffffffu, bmB, 2));

        float mnA = fmaxf(mA, bmA), mnB = fmaxf(mB, bmB);
        float alphaA = __expf(mA - mnA), alphaB = __expf(mB - mnB);
        mA = mnA; mB = mnB;

        uint32_t ph[8][2];
        float sA = 0.f, sB = 0.f;
        #pragma unroll
        for (int j = 0; j < 8; j++){
            float p0 = __expf(S[j][0] - mnA), p1 = __expf(S[j][1] - mnA);
            float p2 = __expf(S[j][2] - mnB), p3 = __expf(S[j][3] - mnB);
            __half2 hA = __floats2half2_rn(p0, p1);
            __half2 hB = __floats2half2_rn(p2, p3);
            float2 fA = __half22float2(hA), fB = __half22float2(hB);
            sA += fA.x + fA.y;  sB += fB.x + fB.y;   // sum exactly what GEMM2 sees
            ph[j][0] = *(uint32_t*)&hA;
            ph[j][1] = *(uint32_t*)&hB;
        }
        sA += __shfl_xor_sync(0xffffffffu, sA, 1);
        sA += __shfl_xor_sync(0xffffffffu, sA, 2);
        sB += __shfl_xor_sync(0xffffffffu, sB, 1);
        sB += __shfl_xor_sync(0xffffffffu, sB, 2);
        lA = lA * alphaA + sA;
        lB = lB * alphaB + sB;

        if (!__all_sync(0xffffffffu, (alphaA == 1.f) & (alphaB == 1.f))){
            #pragma unroll
            for (int j = 0; j < 32; j++){
                acc[j][0] *= alphaA; acc[j][1] *= alphaA;
                acc[j][2] *= alphaB; acc[j][3] *= alphaB;
            }
        }

        // ---- GEMM2: acc[16q x 256d] += P[16q x 64e] * Khi[64e x 256d] -----
        #pragma unroll
        for (int kc = 0; kc < 4; kc++){
            uint32_t a[4] = { ph[2*kc][0], ph[2*kc][1], ph[2*kc+1][0], ph[2*kc+1][1] };
            uint32_t rof = kr2 + (uint32_t)kc*8192u;
            #pragma unroll
            for (int jj = 0; jj < 32; jj += 2){
                uint32_t bb[4];
                ldsm4t(bb, kb + rof + (uint32_t)((((g>>1) + jj) ^ lr) << 4));
                mma16816(acc[jj],   a, bb);
                mma16816(acc[jj+1], a, bb+2);
            }
        }
        // no bottom sync: top-of-next-iter sync protects khi buf reuse
    }

    // ---- epilogue: out[.., 256:512] = acc / l (dec half written by pk_all)
    {
        int rA = 16*w + (lane >> 2);
        float ivA = 1.f / lA, ivB = 1.f / lB;
        float* oA = out + ((size_t)(b*T_ + t0 + rA))    *(size_t)(2*D_) + D_ + (lane&3)*2;
        float* oB = out + ((size_t)(b*T_ + t0 + rA + 8))*(size_t)(2*D_) + D_ + (lane&3)*2;
        #pragma unroll
        for (int j = 0; j < 32; j++){
            *(float2*)(oA + 8*j) = make_float2(acc[j][0]*ivA, acc[j][1]*ivA);
            *(float2*)(oB + 8*j) = make_float2(acc[j][2]*ivB, acc[j][3]*ivB);
        }
    }
}

extern "C" void kernel_launch(void* const* d_in, const int* in_sizes, int n_in,
                              void* d_out, int out_size)
{
    const float* enc = (const float*)d_in[0];  // encoder_outputs [8,2048,256]
    const float* dec = (const float*)d_in[1];  // decoder_outputs [8,2048,256]
    float* out = (float*)d_out;                // [8,2048,512]
    (void)in_sizes; (void)n_in; (void)out_size;

    const int quads2 = 2 * B_*T_*D_/4;         // dec + enc quads
    pk_all<<<quads2/NTH, NTH>>>(dec, enc, out);

    cudaFuncSetAttribute(attn_main, cudaFuncAttributeMaxDynamicSharedMemorySize, SM_TOT);
    dim3 grid(T_/BQ, B_);                      // (16, 8) = 128 CTAs, single wave
    attn_main<<<grid, NTH, SM_TOT>>>(out);
}